// round 10
// baseline (speedup 1.0000x reference)
#include <cuda_runtime.h>
#include <cuda_fp16.h>
#include <cstdint>

#define MAX_N 100000
#define MAX_E 1600000
#define D 64

#define SCAN_T 1024
#define SCAN_V 4
#define SCAN_TILE (SCAN_T * SCAN_V)   // 4096 -> 25 tiles for N=100000
#define GRAB 8                         // rows per warp work-grab

// Zeroed-every-call scratch (single memset node)
struct WS {
    int hist[MAX_N];                      // row degree histogram
    unsigned long long state[32];         // lookback state: (flag<<32)|value
    int counter;                          // dynamic row counter for accum
};
__device__ WS    g_ws;
__device__ int   g_off[MAX_N + 1];        // CSR row offsets
__device__ int   g_cur[MAX_N];            // scatter cursors (written by scan)
__device__ int2  g_pairs[MAX_E];          // row-sorted (col, val_bits)
__device__ uint4 g_emb_h[MAX_N * 8];      // fp16 embeddings: 32 x u32 (=64 halves) per row

__device__ __forceinline__ unsigned long long ldv(const unsigned long long* p) {
    return *(volatile const unsigned long long*)p;
}
__device__ __forceinline__ void stv(unsigned long long* p, unsigned long long v) {
    *(volatile unsigned long long*)p = v;
}

// ---- Histogram of rows (4 edges/thread, vectorized) ----
__global__ void k_hist(const int* __restrict__ rows, int nE) {
    int i = blockIdx.x * blockDim.x + threadIdx.x;
    int e = i * 4;
    if (e + 3 < nE) {
        int4 r = *reinterpret_cast<const int4*>(rows + e);
        atomicAdd(&g_ws.hist[r.x], 1);
        atomicAdd(&g_ws.hist[r.y], 1);
        atomicAdd(&g_ws.hist[r.z], 1);
        atomicAdd(&g_ws.hist[r.w], 1);
    } else {
        for (int k = e; k < nE; k++) atomicAdd(&g_ws.hist[rows[k]], 1);
    }
}

// ---- Fused: decoupled-lookback scan (blocks < nTiles) + fp16 convert (rest) ----
__global__ void __launch_bounds__(SCAN_T)
k_scan(const float* __restrict__ emb, int nConvItems,
       int n, int nE, int nTiles) {
    int b = blockIdx.x;

    if (b >= nTiles) {
        // fp32 -> fp16 convert: 8 floats -> uint4 per thread
        int i = (b - nTiles) * SCAN_T + threadIdx.x;
        if (i < nConvItems) {
            float4 f0 = reinterpret_cast<const float4*>(emb)[i * 2];
            float4 f1 = reinterpret_cast<const float4*>(emb)[i * 2 + 1];
            __half2 a = __floats2half2_rn(f0.x, f0.y);
            __half2 bb = __floats2half2_rn(f0.z, f0.w);
            __half2 c = __floats2half2_rn(f1.x, f1.y);
            __half2 d = __floats2half2_rn(f1.z, f1.w);
            uint4 p;
            p.x = *reinterpret_cast<unsigned*>(&a);
            p.y = *reinterpret_cast<unsigned*>(&bb);
            p.z = *reinterpret_cast<unsigned*>(&c);
            p.w = *reinterpret_cast<unsigned*>(&d);
            g_emb_h[i] = p;
        }
        return;
    }

    __shared__ int warp_sums[32];
    __shared__ int s_prefix;

    int t    = threadIdx.x;
    int lane = t & 31;
    int wid  = t >> 5;
    int idx  = b * SCAN_TILE + t * 4;

    int4 hv = make_int4(0, 0, 0, 0);
    if (idx + 3 < n) {
        hv = *reinterpret_cast<const int4*>(&g_ws.hist[idx]);
    } else if (idx < n) {
        hv.x = g_ws.hist[idx];
        if (idx + 1 < n) hv.y = g_ws.hist[idx + 1];
        if (idx + 2 < n) hv.z = g_ws.hist[idx + 2];
    }
    int tsum = hv.x + hv.y + hv.z + hv.w;

    int x = tsum;
    #pragma unroll
    for (int d = 1; d < 32; d <<= 1) {
        int y = __shfl_up_sync(~0u, x, d);
        if (lane >= d) x += y;
    }
    if (lane == 31) warp_sums[wid] = x;
    __syncthreads();
    if (wid == 0) {
        int s = warp_sums[lane];
        #pragma unroll
        for (int d = 1; d < 32; d <<= 1) {
            int y = __shfl_up_sync(~0u, s, d);
            if (lane >= d) s += y;
        }
        warp_sums[lane] = s;
    }
    __syncthreads();

    int texcl     = (x - tsum) + (wid > 0 ? warp_sums[wid - 1] : 0);
    int block_agg = warp_sums[31];

    if (wid == 0) {
        if (b == 0) {
            if (lane == 0) {
                stv(&g_ws.state[0], (2ULL << 32) | (unsigned)block_agg);
                s_prefix = 0;
            }
        } else {
            if (lane == 0)
                stv(&g_ws.state[b], (1ULL << 32) | (unsigned)block_agg);
            int j = b - 1 - lane;
            int f = 2, v = 0;
            for (;;) {
                if (j >= 0) {
                    unsigned long long s = ldv(&g_ws.state[j]);
                    f = (int)(s >> 32);
                    v = (int)(unsigned)s;
                }
                if (__all_sync(~0u, f != 0)) break;
            }
            unsigned m2    = __ballot_sync(~0u, f == 2);
            int      first = __ffs(m2) - 1;
            int contrib = (lane <= first) ? v : 0;
            #pragma unroll
            for (int d = 16; d > 0; d >>= 1)
                contrib += __shfl_down_sync(~0u, contrib, d);
            int ep = __shfl_sync(~0u, contrib, 0);
            if (lane == 0) {
                stv(&g_ws.state[b], (2ULL << 32) | (unsigned)(ep + block_agg));
                s_prefix = ep;
            }
        }
    }
    __syncthreads();

    int bp = s_prefix;
    int o0 = bp + texcl;
    int o1 = o0 + hv.x;
    int o2 = o1 + hv.y;
    int o3 = o2 + hv.z;
    if (idx + 3 < n) {
        *reinterpret_cast<int4*>(&g_off[idx]) = make_int4(o0, o1, o2, o3);
        *reinterpret_cast<int4*>(&g_cur[idx]) = make_int4(o0, o1, o2, o3);
    } else if (idx < n) {
        g_off[idx] = o0; g_cur[idx] = o0;
        if (idx + 1 < n) { g_off[idx + 1] = o1; g_cur[idx + 1] = o1; }
        if (idx + 2 < n) { g_off[idx + 2] = o2; g_cur[idx + 2] = o2; }
    }
    if (b == 0 && t == 0) g_off[n] = nE;
}

// ---- Scatter into row-sorted order (vectorized, cursor-only atomics) ----
__global__ void k_scatter(const int* __restrict__ rows,
                          const int* __restrict__ cols,
                          const float* __restrict__ vals, int nE) {
    int i = blockIdx.x * blockDim.x + threadIdx.x;
    int e = i * 4;
    if (e + 3 < nE) {
        int4   r = *reinterpret_cast<const int4*>(rows + e);
        int4   c = *reinterpret_cast<const int4*>(cols + e);
        float4 v = *reinterpret_cast<const float4*>(vals + e);
        int p0 = atomicAdd(&g_cur[r.x], 1);
        int p1 = atomicAdd(&g_cur[r.y], 1);
        int p2 = atomicAdd(&g_cur[r.z], 1);
        int p3 = atomicAdd(&g_cur[r.w], 1);
        g_pairs[p0] = make_int2(c.x, __float_as_int(v.x));
        g_pairs[p1] = make_int2(c.y, __float_as_int(v.y));
        g_pairs[p2] = make_int2(c.z, __float_as_int(v.z));
        g_pairs[p3] = make_int2(c.w, __float_as_int(v.w));
    } else {
        for (int k = e; k < nE; k++) {
            int pos = atomicAdd(&g_cur[rows[k]], 1);
            g_pairs[pos] = make_int2(cols[k], __float_as_int(vals[k]));
        }
    }
}

// one edge: uniform (col,val) + per-lane 4B gather (2 halves) -> 2 fp32 fmas
#define ACC1(col, vbits, acc) do {                                          \
    const unsigned* rp = reinterpret_cast<const unsigned*>(g_emb_h) +       \
                         (size_t)(col) * 32 + lane;                         \
    unsigned hbits = *rp;                                                   \
    float2 f = __half22float2(*reinterpret_cast<const __half2*>(&hbits));   \
    float v = __int_as_float(vbits);                                        \
    (acc).x = fmaf(v, f.x, (acc).x);                                        \
    (acc).y = fmaf(v, f.y, (acc).y);                                        \
} while (0)

// ---- Accumulate: warp-per-row, dynamic row grabbing (perfect balance) ----
__global__ void __launch_bounds__(256)
k_accum(float* __restrict__ out, int n) {
    int lane = threadIdx.x & 31;

    for (;;) {
        int base = 0;
        if (lane == 0) base = atomicAdd(&g_ws.counter, GRAB);
        base = __shfl_sync(~0u, base, 0);
        if (base >= n) return;
        int rend = min(base + GRAB, n);

        for (int row = base; row < rend; row++) {
            int s = g_off[row];
            int e = g_off[row + 1];

            float2 acc = make_float2(0.f, 0.f);
            int i = s;
            if ((i & 1) && i < e) {         // align int4 pair loads
                int2 p = g_pairs[i];
                ACC1(p.x, p.y, acc);
                i++;
            }
            for (; i + 8 <= e; i += 8) {    // 8 independent 4B gathers in flight
                int4 q0 = *reinterpret_cast<const int4*>(&g_pairs[i]);
                int4 q1 = *reinterpret_cast<const int4*>(&g_pairs[i + 2]);
                int4 q2 = *reinterpret_cast<const int4*>(&g_pairs[i + 4]);
                int4 q3 = *reinterpret_cast<const int4*>(&g_pairs[i + 6]);
                ACC1(q0.x, q0.y, acc); ACC1(q0.z, q0.w, acc);
                ACC1(q1.x, q1.y, acc); ACC1(q1.z, q1.w, acc);
                ACC1(q2.x, q2.y, acc); ACC1(q2.z, q2.w, acc);
                ACC1(q3.x, q3.y, acc); ACC1(q3.z, q3.w, acc);
            }
            for (; i + 2 <= e; i += 2) {
                int4 q = *reinterpret_cast<const int4*>(&g_pairs[i]);
                ACC1(q.x, q.y, acc); ACC1(q.z, q.w, acc);
            }
            if (i < e) {
                int2 p = g_pairs[i];
                ACC1(p.x, p.y, acc);
            }

            // lane owns out[row*64 + lane*2 .. +2): coalesced float2 store
            *reinterpret_cast<float2*>(out + (size_t)row * D + lane * 2) = acc;
        }
    }
}

extern "C" void kernel_launch(void* const* d_in, const int* in_sizes, int n_in,
                              void* d_out, int out_size)
{
    const float* emb  = (const float*)d_in[0];   // [N, 64]
    const float* vals = (const float*)d_in[1];   // [E]
    const int*   rows = (const int*)  d_in[2];   // [E]
    const int*   cols = (const int*)  d_in[3];   // [E]
    float* out = (float*)d_out;                  // [N, 64]

    int nE = in_sizes[1];
    int nN = in_sizes[0] / D;

    void* ws_ptr = nullptr;
    cudaGetSymbolAddress(&ws_ptr, g_ws);
    cudaMemsetAsync(ws_ptr, 0, sizeof(WS), 0);

    int nConvItems = nN * (D / 8);                    // uint4s in fp16 table
    int gConv  = (nConvItems + SCAN_T - 1) / SCAN_T;  // conv blocks (1024 thr)
    int gHist  = (nE / 4 + 255) / 256 + 1;
    int nTiles = (nN + SCAN_TILE - 1) / SCAN_TILE;    // <=32

    k_hist   <<<gHist, 256>>>(rows, nE);
    k_scan   <<<nTiles + gConv, SCAN_T>>>(emb, nConvItems, nN, nE, nTiles);
    k_scatter<<<gHist, 256>>>(rows, cols, vals, nE);
    k_accum  <<<148 * 6, 256>>>(out, nN);
}